// round 15
// baseline (speedup 1.0000x reference)
#include <cuda_runtime.h>
#include <cuda_bf16.h>
#include <cuda_fp16.h>
#include <stdint.h>
#include <math.h>

typedef __nv_bfloat16 bf16;
typedef unsigned int u32;

// ---------------- problem constants ----------------
#define BB 4
#define CCH 512
#define CIn 256
#define NN 12544
#define MMr 1568          // real pooled positions
#define MP_Y 1600         // pad for y-GEMM K (25*64)
#define MP_F 1664         // pad for f-GEMM N (13*128)
#define EPS 1e-5f

// ---------------- scratch layout (byte offsets) ----------------
#define XT_HI    0ULL
#define XT_LO    51380224ULL
#define XT_F16   102760448ULL
#define F_OFF    0ULL
#define CONV_HI  334987264ULL                   // [theta_hi | phi_hi]
#define G16_OFF  386367488ULL                   // g conv out, fp16 single plane
#define CONV_LO  412057600ULL                   // [theta_lo | phi_lo]
#define P_F16    334987264ULL
#define Y_F16    0ULL
#define WY_OFF   102760448ULL                   // fp16 wy
#define GT_F16   656113664ULL
#define PHP_HI   662667264ULL
#define PHP_LO   666075136ULL
#define W8_OFF   669483008ULL
#define BCAT_OFF 671580160ULL
#define PART_OFF 671583232ULL
#define SCRATCH_BYTES 672000000ULL

#define CONV_PLANE 25690112ULL   // bytes per conv plane (4*NN*256*2)

__device__ __align__(128) unsigned char d_scratch[SCRATCH_BYTES];
__device__ __align__(16) float d_stats[2 * CCH];

// ---------------- helpers ----------------
__device__ __forceinline__ u32 smem_u32(const void* p) {
    u32 a;
    asm("{ .reg .u64 t; cvta.to.shared.u64 t, %1; cvt.u32.u64 %0, t; }" : "=r"(a) : "l"(p));
    return a;
}
__device__ __forceinline__ void ldsm4(u32& r0, u32& r1, u32& r2, u32& r3, u32 addr) {
    asm volatile("ldmatrix.sync.aligned.m8n8.x4.shared.b16 {%0,%1,%2,%3}, [%4];"
                 : "=r"(r0), "=r"(r1), "=r"(r2), "=r"(r3) : "r"(addr));
}
template <int F16>
__device__ __forceinline__ void mma16816(float* d, const u32* a, const u32* b) {
    if (F16)
        asm volatile(
            "mma.sync.aligned.m16n8k16.row.col.f32.f16.f16.f32 "
            "{%0,%1,%2,%3},{%4,%5,%6,%7},{%8,%9},{%0,%1,%2,%3};"
            : "+f"(d[0]), "+f"(d[1]), "+f"(d[2]), "+f"(d[3])
            : "r"(a[0]), "r"(a[1]), "r"(a[2]), "r"(a[3]), "r"(b[0]), "r"(b[1]));
    else
        asm volatile(
            "mma.sync.aligned.m16n8k16.row.col.f32.bf16.bf16.f32 "
            "{%0,%1,%2,%3},{%4,%5,%6,%7},{%8,%9},{%0,%1,%2,%3};"
            : "+f"(d[0]), "+f"(d[1]), "+f"(d[2]), "+f"(d[3])
            : "r"(a[0]), "r"(a[1]), "r"(a[2]), "r"(a[3]), "r"(b[0]), "r"(b[1]));
}
__device__ __forceinline__ u32 sw128(u32 off) { return off ^ ((off >> 3) & 0x70); }
__device__ __forceinline__ void cp16(u32 dst, const void* src) {
    asm volatile("cp.async.cg.shared.global [%0], [%1], 16;" :: "r"(dst), "l"(src));
}
#define CP_COMMIT() asm volatile("cp.async.commit_group;" ::: "memory")
#define CP_WAIT1()  asm volatile("cp.async.wait_group 1;" ::: "memory")

// ---------------- cp.async split 16-bit GEMM (R7-validated core) ----------------
// Passes: 0 = A_hi*B_hi^T, 1 = A_hi*B_lo^T, 2 = A_lo*B_hi^T.
// NP=3: full 3-term split. NP=1: plain A_hi*B_hi^T.
// CTA tile 128x128, BK=64, 8 warps (2M x 4N), 3-stage cp.async ring, 2 CTAs/SM.
// EPI 0: fp32 C + optional col bias. EPI 1: bf16 hi/lo planes. EPI 2: single fp16 plane.
// SEG 1: 256-col segmented output (fused conv). F16: fp16 mma instead of bf16.
template <int EPI, int SEG, int NP, int F16>
__global__ __launch_bounds__(256, 2)
void tgemm(const bf16* __restrict__ Ahi, const bf16* __restrict__ Alo,
           const bf16* __restrict__ Bhi, const bf16* __restrict__ Blo,
           float* __restrict__ Cf, bf16* __restrict__ Chi, bf16* __restrict__ Clo,
           const float* __restrict__ bias,
           int K, int ldc, long long sA, long long sB, long long sC, long long segS)
{
    extern __shared__ __align__(1024) unsigned char sm[];
    const u32 sbase = smem_u32(sm);
    const int tid = threadIdx.x;
    const int wid = tid >> 5;
    const int lane = tid & 31;
    const int m0 = blockIdx.x * 128;
    const int n0 = blockIdx.y * 128;
    const long long bz = blockIdx.z;
    Ahi += bz * sA; Alo += bz * sA;
    Bhi += bz * sB; Blo += bz * sB;

    const int Kc = K >> 6;
    const int total = NP * Kc;

    const int rowL = tid >> 1;
    const int segb = (tid & 1) * 32;
    const long long gA = (long long)(m0 + rowL) * K + segb;
    const long long gB = (long long)(n0 + rowL) * K + segb;
    u32 soff[4];
#pragma unroll
    for (int i = 0; i < 4; i++)
        soff[i] = sw128((u32)rowL * 128 + (u32)segb * 2 + i * 16);

#define ISSUE(it2) do { \
    const int _p = (it2) / Kc; \
    const int _k0 = ((it2) - _p * Kc) << 6; \
    const bf16* _A = (_p == 2) ? Alo : Ahi; \
    const bf16* _B = (_p == 1) ? Blo : Bhi; \
    const u32 _sa = sbase + ((it2) % 3) * 32768u; \
    const u32 _sb = _sa + 16384u; \
    _Pragma("unroll") \
    for (int _i = 0; _i < 4; _i++) { \
        cp16(_sa + soff[_i], _A + gA + _k0 + _i * 8); \
        cp16(_sb + soff[_i], _B + gB + _k0 + _i * 8); \
    } \
} while (0)

    const int wm = wid >> 2;
    const int wn = wid & 3;
    const int rowA = wm * 64 + ((lane >> 3) & 1) * 8 + (lane & 7);
    const u32 kbA = (u32)(lane >> 4) * 16;
    const int rowB = wn * 32 + ((lane >> 4) & 1) * 8 + (lane & 7);
    const u32 kbB = (u32)((lane >> 3) & 1) * 16;

    float acc[4][4][4];
#pragma unroll
    for (int mt = 0; mt < 4; mt++)
#pragma unroll
        for (int nt = 0; nt < 4; nt++)
#pragma unroll
            for (int q = 0; q < 4; q++) acc[mt][nt][q] = 0.f;

    ISSUE(0); CP_COMMIT();
    ISSUE(1); CP_COMMIT();

    for (int it = 0; it < total; it++) {
        CP_WAIT1();
        __syncthreads();
        if (it + 2 < total) ISSUE(it + 2);
        CP_COMMIT();

        const u32 sA32 = sbase + (it % 3) * 32768u;
        const u32 sB32 = sA32 + 16384u;
#pragma unroll
        for (int kk = 0; kk < 4; kk++) {
            u32 af[4][4];
#pragma unroll
            for (int mt = 0; mt < 4; mt++) {
                u32 off = (u32)(rowA + mt * 16) * 128 + (u32)kk * 32 + kbA;
                ldsm4(af[mt][0], af[mt][1], af[mt][2], af[mt][3], sA32 + sw128(off));
            }
            u32 bfr[2][4];
#pragma unroll
            for (int nt2 = 0; nt2 < 2; nt2++) {
                u32 off = (u32)(rowB + nt2 * 16) * 128 + (u32)kk * 32 + kbB;
                ldsm4(bfr[nt2][0], bfr[nt2][1], bfr[nt2][2], bfr[nt2][3], sB32 + sw128(off));
            }
#pragma unroll
            for (int mt = 0; mt < 4; mt++)
#pragma unroll
                for (int nt = 0; nt < 4; nt++)
                    mma16816<F16>(acc[mt][nt], af[mt], &bfr[nt >> 1][(nt & 1) * 2]);
        }
    }
#undef ISSUE

    const int r0 = m0 + wm * 64 + (lane >> 2);
    const int cb0 = n0 + wn * 32 + (lane & 3) * 2;
    const long long obase = bz * sC + (SEG ? (long long)(n0 >> 8) * segS : 0LL);
#pragma unroll
    for (int nt = 0; nt < 4; nt++) {
        const int c = cb0 + nt * 8;
        const int cl = SEG ? (c & 255) : c;
        const float b0v = bias ? bias[c] : 0.f;
        const float b1v = bias ? bias[c + 1] : 0.f;
#pragma unroll
        for (int mt = 0; mt < 4; mt++) {
            const long long ra = r0 + mt * 16;
            const long long rb = ra + 8;
            float v0 = acc[mt][nt][0] + b0v;
            float v1 = acc[mt][nt][1] + b1v;
            float v2 = acc[mt][nt][2] + b0v;
            float v3 = acc[mt][nt][3] + b1v;
            if (EPI == 0) {
                float* base = Cf + obase;
                *(float2*)(base + ra * ldc + cl) = make_float2(v0, v1);
                *(float2*)(base + rb * ldc + cl) = make_float2(v2, v3);
            } else if (EPI == 2) {
                __half* hp = (__half*)Chi + obase;
                *(__half2*)(hp + ra * ldc + cl) = __floats2half2_rn(v0, v1);
                *(__half2*)(hp + rb * ldc + cl) = __floats2half2_rn(v2, v3);
            } else {
                bf16 h0 = __float2bfloat16(v0), h1 = __float2bfloat16(v1);
                bf16 h2 = __float2bfloat16(v2), h3 = __float2bfloat16(v3);
                bf16 l0 = __float2bfloat16(v0 - __bfloat162float(h0));
                bf16 l1 = __float2bfloat16(v1 - __bfloat162float(h1));
                bf16 l2 = __float2bfloat16(v2 - __bfloat162float(h2));
                bf16 l3 = __float2bfloat16(v3 - __bfloat162float(h3));
                bf16* hb = Chi + obase;
                bf16* lb = Clo + obase;
                *(u32*)(hb + ra * ldc + cl) = (u32)__bfloat16_as_ushort(h0) | ((u32)__bfloat16_as_ushort(h1) << 16);
                *(u32*)(hb + rb * ldc + cl) = (u32)__bfloat16_as_ushort(h2) | ((u32)__bfloat16_as_ushort(h3) << 16);
                *(u32*)(lb + ra * ldc + cl) = (u32)__bfloat16_as_ushort(l0) | ((u32)__bfloat16_as_ushort(l1) << 16);
                *(u32*)(lb + rb * ldc + cl) = (u32)__bfloat16_as_ushort(l2) | ((u32)__bfloat16_as_ushort(l3) << 16);
            }
        }
    }
}

// ---------------- fused-split f-GEMM: all 3 products per 32-K chunk ----------------
// Stage row (128B) packs hi (bytes 0..63) and lo (64..127); stage = 16KB A + 16KB B.
// Compute ordered per-mt to cap live fragment regs (~84 + overhead).
// fp32 output, no bias.
__global__ __launch_bounds__(256, 2)
void tgemm_f(const bf16* __restrict__ Ahi, const bf16* __restrict__ Alo,
             const bf16* __restrict__ Bhi, const bf16* __restrict__ Blo,
             float* __restrict__ Cf,
             int K, int ldc, long long sA, long long sB, long long sC)
{
    extern __shared__ __align__(1024) unsigned char sm[];
    const u32 sbase = smem_u32(sm);
    const int tid = threadIdx.x;
    const int wid = tid >> 5;
    const int lane = tid & 31;
    const int m0 = blockIdx.x * 128;
    const int n0 = blockIdx.y * 128;
    const long long bz = blockIdx.z;

    const int Kc = K >> 5;   // 32-K chunks

    // loads: rowL = tid>>1; half selects hi/lo plane; 4 x 16B = 32 elems
    const int rowL = tid >> 1;
    const int half = tid & 1;
    const bf16* srcA = (half ? Alo : Ahi) + bz * sA;
    const bf16* srcB = (half ? Blo : Bhi) + bz * sB;
    const long long gA = (long long)(m0 + rowL) * K;
    const long long gB = (long long)(n0 + rowL) * K;
    u32 soff[4];
#pragma unroll
    for (int i = 0; i < 4; i++)
        soff[i] = sw128((u32)rowL * 128 + (u32)half * 64 + i * 16);

#define ISSUEF(it2) do { \
    const long long _k0 = (long long)(it2) << 5; \
    const u32 _sa = sbase + ((it2) % 3) * 32768u; \
    const u32 _sb = _sa + 16384u; \
    _Pragma("unroll") \
    for (int _i = 0; _i < 4; _i++) { \
        cp16(_sa + soff[_i], srcA + gA + _k0 + _i * 8); \
        cp16(_sb + soff[_i], srcB + gB + _k0 + _i * 8); \
    } \
} while (0)

    const int wm = wid >> 2;
    const int wn = wid & 3;
    const int rowA = wm * 64 + ((lane >> 3) & 1) * 8 + (lane & 7);
    const u32 kbA = (u32)(lane >> 4) * 16;
    const int rowB = wn * 32 + ((lane >> 4) & 1) * 8 + (lane & 7);
    const u32 kbB = (u32)((lane >> 3) & 1) * 16;

    float acc[4][4][4];
#pragma unroll
    for (int mt = 0; mt < 4; mt++)
#pragma unroll
        for (int nt = 0; nt < 4; nt++)
#pragma unroll
            for (int q = 0; q < 4; q++) acc[mt][nt][q] = 0.f;

    ISSUEF(0); CP_COMMIT();
    ISSUEF(1); CP_COMMIT();

    for (int it = 0; it < Kc; it++) {
        CP_WAIT1();
        __syncthreads();
        if (it + 2 < Kc) ISSUEF(it + 2);
        CP_COMMIT();

        const u32 sA32 = sbase + (it % 3) * 32768u;
        const u32 sB32 = sA32 + 16384u;
#pragma unroll
        for (int kk = 0; kk < 2; kk++) {
            u32 bh[2][4], bl[2][4];
#pragma unroll
            for (int nt2 = 0; nt2 < 2; nt2++) {
                u32 off = (u32)(rowB + nt2 * 16) * 128 + (u32)kk * 32 + kbB;
                ldsm4(bh[nt2][0], bh[nt2][1], bh[nt2][2], bh[nt2][3], sB32 + sw128(off));
                ldsm4(bl[nt2][0], bl[nt2][1], bl[nt2][2], bl[nt2][3], sB32 + sw128(off + 64));
            }
#pragma unroll
            for (int mt = 0; mt < 4; mt++) {
                const u32 offA = (u32)(rowA + mt * 16) * 128 + (u32)kk * 32 + kbA;
                u32 a0, a1, a2, a3;
                ldsm4(a0, a1, a2, a3, sA32 + sw128(offA));          // A_hi
                {
                    u32 a[4] = {a0, a1, a2, a3};
#pragma unroll
                    for (int nt = 0; nt < 4; nt++)
                        mma16816<0>(acc[mt][nt], a, &bh[nt >> 1][(nt & 1) * 2]);
#pragma unroll
                    for (int nt = 0; nt < 4; nt++)
                        mma16816<0>(acc[mt][nt], a, &bl[nt >> 1][(nt & 1) * 2]);
                }
                ldsm4(a0, a1, a2, a3, sA32 + sw128(offA + 64));     // A_lo
                {
                    u32 a[4] = {a0, a1, a2, a3};
#pragma unroll
                    for (int nt = 0; nt < 4; nt++)
                        mma16816<0>(acc[mt][nt], a, &bh[nt >> 1][(nt & 1) * 2]);
                }
            }
        }
    }
#undef ISSUEF

    const int r0 = m0 + wm * 64 + (lane >> 2);
    const int cb0 = n0 + wn * 32 + (lane & 3) * 2;
    float* base = Cf + bz * sC;
#pragma unroll
    for (int nt = 0; nt < 4; nt++) {
        const int c = cb0 + nt * 8;
#pragma unroll
        for (int mt = 0; mt < 4; mt++) {
            const long long ra = r0 + mt * 16;
            const long long rb = ra + 8;
            *(float2*)(base + ra * ldc + c) = make_float2(acc[mt][nt][0], acc[mt][nt][1]);
            *(float2*)(base + rb * ldc + c) = make_float2(acc[mt][nt][2], acc[mt][nt][3]);
        }
    }
}

// ---------------- prep: theta/phi bf16 hi/lo, g/W fp16 single; bias concat ----------------
__global__ void prep_kernel(const float* __restrict__ tw, const float* __restrict__ pw,
                            const float* __restrict__ gw, const float* __restrict__ ww,
                            const float* __restrict__ tb, const float* __restrict__ pb,
                            const float* __restrict__ gb,
                            bf16* __restrict__ wcat_hi, bf16* __restrict__ wcat_lo,
                            __half* __restrict__ gw16, __half* __restrict__ ww16,
                            float* __restrict__ bcat)
{
    const int i = blockIdx.x * 256 + threadIdx.x;
    const int t = i >> 17;
    const int j = i & 131071;
    const float* src = (t == 0) ? tw : (t == 1) ? pw : (t == 2) ? gw : ww;
    const float v = src[j];
    if (t < 2) {
        const bf16 h = __float2bfloat16(v);
        wcat_hi[t * 131072 + j] = h;
        wcat_lo[t * 131072 + j] = __float2bfloat16(v - __bfloat162float(h));
    } else if (t == 2) {
        gw16[j] = __float2half(v);
    } else {
        ww16[j] = __float2half(v);
    }
    if (i < 768) {
        const float* bs = (i < 256) ? tb : (i < 512) ? pb : gb;
        bcat[i] = bs[i & 255];
    }
}

// ---------------- zero fill ----------------
__global__ void zero_kernel(float4* __restrict__ p, long long n4)
{
    long long i = (long long)blockIdx.x * 256 + threadIdx.x;
    const long long stride = (long long)gridDim.x * 256;
    for (; i < n4; i += stride) p[i] = make_float4(0.f, 0.f, 0.f, 0.f);
}

// ---------------- transpose x (b,512,N) -> xT bf16 hi/lo + fp16 plane ----------------
__global__ void xpose_kernel(const float* __restrict__ x, bf16* __restrict__ xhi,
                             bf16* __restrict__ xlo, __half* __restrict__ xf)
{
    __shared__ float t[32][33];
    const int b = blockIdx.z;
    const int n0 = blockIdx.x * 32;
    const int c0 = blockIdx.y * 32;
    const int tx = threadIdx.x, ty = threadIdx.y;
    const float* xb = x + (long long)b * CCH * NN;
#pragma unroll
    for (int k = 0; k < 4; k++)
        t[ty + k * 8][tx] = xb[(long long)(c0 + ty + k * 8) * NN + n0 + tx];
    __syncthreads();
    bf16* hb = xhi + (long long)b * NN * CCH;
    bf16* lb = xlo + (long long)b * NN * CCH;
    __half* fb = xf + (long long)b * NN * CCH;
#pragma unroll
    for (int k = 0; k < 4; k++) {
        float v = t[tx][ty + k * 8];
        long long o = (long long)(n0 + ty + k * 8) * CCH + c0 + tx;
        bf16 h = __float2bfloat16(v);
        hb[o] = h;
        lb[o] = __float2bfloat16(v - __bfloat162float(h));
        fb[o] = __float2half(v);
    }
}

// ---------------- 2x2x2 maxpool: g from fp16 plane, phi from bf16 hi/lo ----------------
__global__ void pool_kernel(const __half* __restrict__ g16,
                            const bf16* __restrict__ pH, const bf16* __restrict__ pL,
                            __half* __restrict__ gT,
                            bf16* __restrict__ phphi, bf16* __restrict__ phplo)
{
    const int m = blockIdx.x;
    const int b = blockIdx.y;
    const int ci = threadIdx.x;
    const int tp = m / 196;
    const int r = m % 196;
    const int hp = r / 14;
    const int wp = r % 14;
    const long long bb = (long long)b * NN;
    float gm = -1e30f, pm = -1e30f;
#pragma unroll
    for (int dt = 0; dt < 2; dt++)
#pragma unroll
        for (int dh = 0; dh < 2; dh++)
#pragma unroll
            for (int dw = 0; dw < 2; dw++) {
                const long long n = (long long)(2 * tp + dt) * 784 + (2 * hp + dh) * 28 + (2 * wp + dw);
                const long long o = (bb + n) * CIn + ci;
                float gv = __half2float(g16[o]);
                float pv = __bfloat162float(pH[o]) + __bfloat162float(pL[o]);
                gm = fmaxf(gm, gv);
                pm = fmaxf(pm, pv);
            }
    {
        long long o = ((long long)b * MP_F + m) * CIn + ci;
        bf16 h = __float2bfloat16(pm);
        phphi[o] = h;
        phplo[o] = __float2bfloat16(pm - __bfloat162float(h));
    }
    gT[((long long)b * CIn + ci) * MP_Y + m] = __float2half(gm);
}

// ---------------- softmax: float4 reads; writes p as one fp16 plane ----------------
__global__ __launch_bounds__(256)
void softmax_kernel(const float* __restrict__ f, __half* __restrict__ pout)
{
    __shared__ float row[MMr];
    __shared__ float red[8];
    const long long r = blockIdx.x;
    const float* p = f + r * MP_F;
    __half* oh = pout + r * MP_Y;
    const int tid = threadIdx.x;
    const int wid = tid >> 5, lane = tid & 31;

    float mx = -1e30f;
    for (int i4 = tid; i4 < MMr / 4; i4 += 256) {
        float4 v = ((const float4*)p)[i4];
        *(float4*)&row[i4 * 4] = v;
        mx = fmaxf(fmaxf(mx, fmaxf(v.x, v.y)), fmaxf(v.z, v.w));
    }
#pragma unroll
    for (int s = 16; s > 0; s >>= 1) mx = fmaxf(mx, __shfl_xor_sync(~0u, mx, s));
    if (lane == 0) red[wid] = mx;
    __syncthreads();
    {
        float t = red[lane & 7];
#pragma unroll
        for (int s = 4; s > 0; s >>= 1) t = fmaxf(t, __shfl_xor_sync(~0u, t, s));
        mx = t;
    }

    float sum = 0.f;
    for (int i = tid; i < MMr; i += 256) {
        float e = __expf(row[i] - mx);
        row[i] = e;
        sum += e;
    }
#pragma unroll
    for (int s = 16; s > 0; s >>= 1) sum += __shfl_xor_sync(~0u, sum, s);
    __syncthreads();
    if (lane == 0) red[wid] = sum;
    __syncthreads();
    {
        float t = red[lane & 7];
#pragma unroll
        for (int s = 4; s > 0; s >>= 1) t += __shfl_xor_sync(~0u, t, s);
        sum = t;
    }
    const float inv = 1.f / sum;

    for (int i = tid; i < MMr; i += 256)
        oh[i] = __float2half(row[i] * inv);
    if (tid < MP_Y - MMr)
        oh[MMr + tid] = __ushort_as_half(0);
}

// ---------------- BN stats from fp16 wy ----------------
__global__ void stats_part(const __half* __restrict__ wy, float* __restrict__ part)
{
    const int c = blockIdx.x * 128 + threadIdx.x;
    const int rb = blockIdx.y;
    const __half* p = wy + (long long)rb * 512 * CCH + c;
    float s = 0.f, ss = 0.f;
    for (int r = 0; r < 512; r++) {
        float v = __half2float(p[(long long)r * CCH]);
        s += v;
        ss += v * v;
    }
    part[(long long)rb * 1024 + c] = s;
    part[(long long)rb * 1024 + 512 + c] = ss;
}

__global__ void stats_fin(const float* __restrict__ part, float* __restrict__ stats)
{
    const int c = threadIdx.x;
    float s = 0.f, ss = 0.f;
    for (int r = 0; r < 98; r++) {
        s += part[r * 1024 + c];
        ss += part[r * 1024 + 512 + c];
    }
    const float cnt = (float)BB * (float)NN;
    const float mean = s / cnt;
    const float var = ss / cnt - mean * mean;
    stats[c] = mean;
    stats[CCH + c] = rsqrtf(var + EPS);
}

// ---------------- final: transpose fp16 wy, BN affine + residual ----------------
__global__ void final_kernel(const __half* __restrict__ wy, const float* __restrict__ x,
                             const float* __restrict__ gamma, const float* __restrict__ beta,
                             const float* __restrict__ stats, float* __restrict__ out)
{
    __shared__ __half t[32][34];
    const int b = blockIdx.z;
    const int n0 = blockIdx.x * 32;
    const int c0 = blockIdx.y * 32;
    const int tx = threadIdx.x, ty = threadIdx.y;
    const __half* wb = wy + (long long)b * NN * CCH;
#pragma unroll
    for (int k = 0; k < 4; k++)
        t[ty + k * 8][tx] = wb[(long long)(n0 + ty + k * 8) * CCH + c0 + tx];
    __syncthreads();
#pragma unroll
    for (int k = 0; k < 4; k++) {
        const int c = c0 + ty + k * 8;
        const float mean = stats[c];
        const float rstd = stats[CCH + c];
        const float gs = gamma[c] * rstd;
        const float off = beta[c] - mean * gs;
        const long long o = ((long long)b * CCH + c) * NN + n0 + tx;
        out[o] = __half2float(t[tx][ty + k * 8]) * gs + off + x[o];
    }
}

// ---------------- launch ----------------
extern "C" void kernel_launch(void* const* d_in, const int* in_sizes, int n_in,
                              void* d_out, int out_size)
{
    const float* x       = (const float*)d_in[0];
    const float* g_w     = (const float*)d_in[1];
    const float* g_b     = (const float*)d_in[2];
    const float* theta_w = (const float*)d_in[3];
    const float* theta_b = (const float*)d_in[4];
    const float* phi_w   = (const float*)d_in[5];
    const float* phi_b   = (const float*)d_in[6];
    const float* W_w     = (const float*)d_in[7];
    // d_in[8] = W_b: constant channel bias cancels exactly in training-mode BN — skipped.
    const float* gamma   = (const float*)d_in[9];
    const float* beta    = (const float*)d_in[10];
    float* out = (float*)d_out;

    unsigned char* S = nullptr;
    float* stats = nullptr;
    cudaGetSymbolAddress((void**)&S, d_scratch);
    cudaGetSymbolAddress((void**)&stats, d_stats);

    bf16* xt_hi  = (bf16*)(S + XT_HI);
    bf16* xt_lo  = (bf16*)(S + XT_LO);
    __half* xt16 = (__half*)(S + XT_F16);
    float* f     = (float*)(S + F_OFF);
    bf16* conv_hi = (bf16*)(S + CONV_HI);
    bf16* conv_lo = (bf16*)(S + CONV_LO);
    bf16* th_hi  = conv_hi;
    bf16* th_lo  = conv_lo;
    bf16* pc_hi  = (bf16*)(S + CONV_HI + CONV_PLANE);
    bf16* pc_lo  = (bf16*)(S + CONV_LO + CONV_PLANE);
    __half* g16  = (__half*)(S + G16_OFF);
    __half* p16  = (__half*)(S + P_F16);
    __half* y16  = (__half*)(S + Y_F16);
    __half* wy   = (__half*)(S + WY_OFF);
    __half* gt16 = (__half*)(S + GT_F16);
    bf16* php_hi = (bf16*)(S + PHP_HI);
    bf16* php_lo = (bf16*)(S + PHP_LO);
    bf16* wcat_hi = (bf16*)(S + W8_OFF);
    bf16* wcat_lo = (bf16*)(S + W8_OFF + 524288);
    __half* gw16 = (__half*)(S + W8_OFF + 1048576);
    __half* ww16 = (__half*)(S + W8_OFF + 1310720);
    float* bcat  = (float*)(S + BCAT_OFF);
    float* part  = (float*)(S + PART_OFF);

    const int smem = 3 * 32768;
    cudaFuncSetAttribute(tgemm<2, 0, 1, 1>, cudaFuncAttributeMaxDynamicSharedMemorySize, smem);
    cudaFuncSetAttribute(tgemm<1, 1, 3, 0>, cudaFuncAttributeMaxDynamicSharedMemorySize, smem);
    cudaFuncSetAttribute(tgemm_f, cudaFuncAttributeMaxDynamicSharedMemorySize, smem);

    const long long sXT = (long long)NN * CCH;
    const long long sCI = (long long)NN * CIn;

    // launch 0: weight splits + bias concat
    prep_kernel<<<2048, 256>>>(theta_w, phi_w, g_w, W_w, theta_b, phi_b, g_b,
                               wcat_hi, wcat_lo, gw16, ww16, bcat);

    // launch 1: zero gt/php region
    zero_kernel<<<2048, 256>>>((float4*)(S + GT_F16), 13369344 / 16);

    // launch 2: transpose x -> xT bf16 hi/lo + fp16 plane
    xpose_kernel<<<dim3(NN / 32, CCH / 32, BB), dim3(32, 8)>>>(x, xt_hi, xt_lo, xt16);

    // launch 3: fused conv [theta|phi] 3-pass bf16
    tgemm<1, 1, 3, 0><<<dim3(98, 4, BB), 256, smem>>>(xt_hi, xt_lo, wcat_hi, wcat_lo,
        nullptr, conv_hi, conv_lo, bcat, CCH, CIn, sXT, 0LL, sCI, 4LL * sCI);

    // launch 4: g conv 1-pass fp16
    tgemm<2, 0, 1, 1><<<dim3(98, 2, BB), 256, smem>>>(
        (const bf16*)xt16, (const bf16*)xt16, (const bf16*)gw16, (const bf16*)gw16,
        nullptr, (bf16*)g16, nullptr, bcat + 512, CCH, CIn, sXT, 0LL, sCI, 0LL);

    // launch 5: pool
    pool_kernel<<<dim3(MMr, BB), 256>>>(g16, pc_hi, pc_lo, gt16, php_hi, php_lo);

    // launch 6: f = theta @ phi^T, fused 3-product per-chunk variant
    tgemm_f<<<dim3(98, MP_F / 128, BB), 256, smem>>>(th_hi, th_lo, php_hi, php_lo,
        f, CIn, MP_F, sCI, (long long)MP_F * CIn, (long long)NN * MP_F);

    // launch 7: softmax -> p fp16
    softmax_kernel<<<BB * NN, 256>>>(f, p16);

    // launch 8: y = p @ gT^T, 1-pass fp16
    tgemm<2, 0, 1, 1><<<dim3(98, 2, BB), 256, smem>>>(
        (const bf16*)p16, (const bf16*)p16, (const bf16*)gt16, (const bf16*)gt16,
        nullptr, (bf16*)y16, nullptr, nullptr, MP_Y, CIn, (long long)NN * MP_Y,
        (long long)CIn * MP_Y, sCI, 0LL);

    // launch 9: wy = y @ W^T, 1-pass fp16 -> fp16 wy
    tgemm<2, 0, 1, 1><<<dim3(98, 4, BB), 256, smem>>>(
        (const bf16*)y16, (const bf16*)y16, (const bf16*)ww16, (const bf16*)ww16,
        nullptr, (bf16*)wy, nullptr, nullptr, CIn, CCH, sCI, 0LL, (long long)NN * CCH, 0LL);

    // launches 10-11: BN stats
    stats_part<<<dim3(4, 98), 128>>>(wy, part);
    stats_fin<<<1, 512>>>(part, stats);

    // launch 12: transpose + BN affine + residual
    final_kernel<<<dim3(NN / 32, CCH / 32, BB), dim3(32, 8)>>>(wy, x, gamma, beta, stats, out);
}

// round 16
// speedup vs baseline: 1.0798x; 1.0798x over previous
#include <cuda_runtime.h>
#include <cuda_bf16.h>
#include <cuda_fp16.h>
#include <stdint.h>
#include <math.h>

typedef __nv_bfloat16 bf16;
typedef unsigned int u32;

// ---------------- problem constants ----------------
#define BB 4
#define CCH 512
#define CIn 256
#define NN 12544
#define MMr 1568          // real pooled positions
#define MP_Y 1600         // pad for y-GEMM K (25*64)
#define MP_F 1664         // pad for f-GEMM N (13*128)
#define EPS 1e-5f

// ---------------- scratch layout (byte offsets) ----------------
#define XT_HI    0ULL
#define XT_LO    51380224ULL
#define XT_F16   102760448ULL
#define F_OFF    0ULL
#define CONV_HI  334987264ULL                   // [theta_hi | phi_hi]
#define G16_OFF  386367488ULL                   // g conv out, fp16 single plane
#define CONV_LO  412057600ULL                   // [theta_lo | phi_lo]
#define P_F16    334987264ULL
#define Y_F16    0ULL
#define WY_OFF   102760448ULL                   // fp16 wy
#define GT_F16   656113664ULL
#define PHP_HI   662667264ULL
#define PHP_LO   666075136ULL
#define W8_OFF   669483008ULL
#define BCAT_OFF 671580160ULL
#define PART_OFF 671583232ULL
#define SCRATCH_BYTES 672000000ULL

#define CONV_PLANE 25690112ULL   // bytes per conv plane (4*NN*256*2)

__device__ __align__(128) unsigned char d_scratch[SCRATCH_BYTES];
__device__ __align__(16) float d_stats[2 * CCH];

// ---------------- helpers ----------------
__device__ __forceinline__ u32 smem_u32(const void* p) {
    u32 a;
    asm("{ .reg .u64 t; cvta.to.shared.u64 t, %1; cvt.u32.u64 %0, t; }" : "=r"(a) : "l"(p));
    return a;
}
__device__ __forceinline__ void ldsm4(u32& r0, u32& r1, u32& r2, u32& r3, u32 addr) {
    asm volatile("ldmatrix.sync.aligned.m8n8.x4.shared.b16 {%0,%1,%2,%3}, [%4];"
                 : "=r"(r0), "=r"(r1), "=r"(r2), "=r"(r3) : "r"(addr));
}
template <int F16>
__device__ __forceinline__ void mma16816(float* d, const u32* a, const u32* b) {
    if (F16)
        asm volatile(
            "mma.sync.aligned.m16n8k16.row.col.f32.f16.f16.f32 "
            "{%0,%1,%2,%3},{%4,%5,%6,%7},{%8,%9},{%0,%1,%2,%3};"
            : "+f"(d[0]), "+f"(d[1]), "+f"(d[2]), "+f"(d[3])
            : "r"(a[0]), "r"(a[1]), "r"(a[2]), "r"(a[3]), "r"(b[0]), "r"(b[1]));
    else
        asm volatile(
            "mma.sync.aligned.m16n8k16.row.col.f32.bf16.bf16.f32 "
            "{%0,%1,%2,%3},{%4,%5,%6,%7},{%8,%9},{%0,%1,%2,%3};"
            : "+f"(d[0]), "+f"(d[1]), "+f"(d[2]), "+f"(d[3])
            : "r"(a[0]), "r"(a[1]), "r"(a[2]), "r"(a[3]), "r"(b[0]), "r"(b[1]));
}
__device__ __forceinline__ u32 sw128(u32 off) { return off ^ ((off >> 3) & 0x70); }
__device__ __forceinline__ void cp16(u32 dst, const void* src) {
    asm volatile("cp.async.cg.shared.global [%0], [%1], 16;" :: "r"(dst), "l"(src));
}
#define CP_COMMIT() asm volatile("cp.async.commit_group;" ::: "memory")
#define CP_WAIT1()  asm volatile("cp.async.wait_group 1;" ::: "memory")

// ---------------- cp.async split 16-bit GEMM (R7-validated core) ----------------
// Passes: 0 = A_hi*B_hi^T, 1 = A_hi*B_lo^T, 2 = A_lo*B_hi^T.
// NP=3: full 3-term split. NP=1: plain A_hi*B_hi^T.
// CTA tile 128x128, BK=64, 8 warps (2M x 4N), 3-stage cp.async ring, 2 CTAs/SM.
// EPI 0: fp32 C + optional col bias (cols >= CLIP skipped). EPI 1: bf16 hi/lo planes.
// EPI 2: single fp16 plane.
// SEG 1: 256-col segmented output (fused conv). F16: fp16 mma instead of bf16.
// CLIP: if >0, EPI-0 stores only columns < CLIP.
template <int EPI, int SEG, int NP, int F16, int CLIP>
__global__ __launch_bounds__(256, 2)
void tgemm(const bf16* __restrict__ Ahi, const bf16* __restrict__ Alo,
           const bf16* __restrict__ Bhi, const bf16* __restrict__ Blo,
           float* __restrict__ Cf, bf16* __restrict__ Chi, bf16* __restrict__ Clo,
           const float* __restrict__ bias,
           int K, int ldc, long long sA, long long sB, long long sC, long long segS)
{
    extern __shared__ __align__(1024) unsigned char sm[];
    const u32 sbase = smem_u32(sm);
    const int tid = threadIdx.x;
    const int wid = tid >> 5;
    const int lane = tid & 31;
    const int m0 = blockIdx.x * 128;
    const int n0 = blockIdx.y * 128;
    const long long bz = blockIdx.z;
    Ahi += bz * sA; Alo += bz * sA;
    Bhi += bz * sB; Blo += bz * sB;

    const int Kc = K >> 6;
    const int total = NP * Kc;

    const int rowL = tid >> 1;
    const int segb = (tid & 1) * 32;
    const long long gA = (long long)(m0 + rowL) * K + segb;
    const long long gB = (long long)(n0 + rowL) * K + segb;
    u32 soff[4];
#pragma unroll
    for (int i = 0; i < 4; i++)
        soff[i] = sw128((u32)rowL * 128 + (u32)segb * 2 + i * 16);

#define ISSUE(it2) do { \
    const int _p = (it2) / Kc; \
    const int _k0 = ((it2) - _p * Kc) << 6; \
    const bf16* _A = (_p == 2) ? Alo : Ahi; \
    const bf16* _B = (_p == 1) ? Blo : Bhi; \
    const u32 _sa = sbase + ((it2) % 3) * 32768u; \
    const u32 _sb = _sa + 16384u; \
    _Pragma("unroll") \
    for (int _i = 0; _i < 4; _i++) { \
        cp16(_sa + soff[_i], _A + gA + _k0 + _i * 8); \
        cp16(_sb + soff[_i], _B + gB + _k0 + _i * 8); \
    } \
} while (0)

    const int wm = wid >> 2;
    const int wn = wid & 3;
    const int rowA = wm * 64 + ((lane >> 3) & 1) * 8 + (lane & 7);
    const u32 kbA = (u32)(lane >> 4) * 16;
    const int rowB = wn * 32 + ((lane >> 4) & 1) * 8 + (lane & 7);
    const u32 kbB = (u32)((lane >> 3) & 1) * 16;

    float acc[4][4][4];
#pragma unroll
    for (int mt = 0; mt < 4; mt++)
#pragma unroll
        for (int nt = 0; nt < 4; nt++)
#pragma unroll
            for (int q = 0; q < 4; q++) acc[mt][nt][q] = 0.f;

    ISSUE(0); CP_COMMIT();
    ISSUE(1); CP_COMMIT();

    for (int it = 0; it < total; it++) {
        CP_WAIT1();
        __syncthreads();
        if (it + 2 < total) ISSUE(it + 2);
        CP_COMMIT();

        const u32 sA32 = sbase + (it % 3) * 32768u;
        const u32 sB32 = sA32 + 16384u;
#pragma unroll
        for (int kk = 0; kk < 4; kk++) {
            u32 af[4][4];
#pragma unroll
            for (int mt = 0; mt < 4; mt++) {
                u32 off = (u32)(rowA + mt * 16) * 128 + (u32)kk * 32 + kbA;
                ldsm4(af[mt][0], af[mt][1], af[mt][2], af[mt][3], sA32 + sw128(off));
            }
            u32 bfr[2][4];
#pragma unroll
            for (int nt2 = 0; nt2 < 2; nt2++) {
                u32 off = (u32)(rowB + nt2 * 16) * 128 + (u32)kk * 32 + kbB;
                ldsm4(bfr[nt2][0], bfr[nt2][1], bfr[nt2][2], bfr[nt2][3], sB32 + sw128(off));
            }
#pragma unroll
            for (int mt = 0; mt < 4; mt++)
#pragma unroll
                for (int nt = 0; nt < 4; nt++)
                    mma16816<F16>(acc[mt][nt], af[mt], &bfr[nt >> 1][(nt & 1) * 2]);
        }
    }
#undef ISSUE

    const int r0 = m0 + wm * 64 + (lane >> 2);
    const int cb0 = n0 + wn * 32 + (lane & 3) * 2;
    const long long obase = bz * sC + (SEG ? (long long)(n0 >> 8) * segS : 0LL);
#pragma unroll
    for (int nt = 0; nt < 4; nt++) {
        const int c = cb0 + nt * 8;
        const int cl = SEG ? (c & 255) : c;
        if (CLIP > 0 && c >= CLIP) continue;
        const float b0v = bias ? bias[c] : 0.f;
        const float b1v = bias ? bias[c + 1] : 0.f;
#pragma unroll
        for (int mt = 0; mt < 4; mt++) {
            const long long ra = r0 + mt * 16;
            const long long rb = ra + 8;
            float v0 = acc[mt][nt][0] + b0v;
            float v1 = acc[mt][nt][1] + b1v;
            float v2 = acc[mt][nt][2] + b0v;
            float v3 = acc[mt][nt][3] + b1v;
            if (EPI == 0) {
                float* base = Cf + obase;
                *(float2*)(base + ra * ldc + cl) = make_float2(v0, v1);
                *(float2*)(base + rb * ldc + cl) = make_float2(v2, v3);
            } else if (EPI == 2) {
                __half* hp = (__half*)Chi + obase;
                *(__half2*)(hp + ra * ldc + cl) = __floats2half2_rn(v0, v1);
                *(__half2*)(hp + rb * ldc + cl) = __floats2half2_rn(v2, v3);
            } else {
                bf16 h0 = __float2bfloat16(v0), h1 = __float2bfloat16(v1);
                bf16 h2 = __float2bfloat16(v2), h3 = __float2bfloat16(v3);
                bf16 l0 = __float2bfloat16(v0 - __bfloat162float(h0));
                bf16 l1 = __float2bfloat16(v1 - __bfloat162float(h1));
                bf16 l2 = __float2bfloat16(v2 - __bfloat162float(h2));
                bf16 l3 = __float2bfloat16(v3 - __bfloat162float(h3));
                bf16* hb = Chi + obase;
                bf16* lb = Clo + obase;
                *(u32*)(hb + ra * ldc + cl) = (u32)__bfloat16_as_ushort(h0) | ((u32)__bfloat16_as_ushort(h1) << 16);
                *(u32*)(hb + rb * ldc + cl) = (u32)__bfloat16_as_ushort(h2) | ((u32)__bfloat16_as_ushort(h3) << 16);
                *(u32*)(lb + ra * ldc + cl) = (u32)__bfloat16_as_ushort(l0) | ((u32)__bfloat16_as_ushort(l1) << 16);
                *(u32*)(lb + rb * ldc + cl) = (u32)__bfloat16_as_ushort(l2) | ((u32)__bfloat16_as_ushort(l3) << 16);
            }
        }
    }
}

// ---------------- prep: theta/phi bf16 hi/lo, g/W fp16 single; bias concat ----------------
__global__ void prep_kernel(const float* __restrict__ tw, const float* __restrict__ pw,
                            const float* __restrict__ gw, const float* __restrict__ ww,
                            const float* __restrict__ tb, const float* __restrict__ pb,
                            const float* __restrict__ gb,
                            bf16* __restrict__ wcat_hi, bf16* __restrict__ wcat_lo,
                            __half* __restrict__ gw16, __half* __restrict__ ww16,
                            float* __restrict__ bcat)
{
    const int i = blockIdx.x * 256 + threadIdx.x;
    const int t = i >> 17;
    const int j = i & 131071;
    const float* src = (t == 0) ? tw : (t == 1) ? pw : (t == 2) ? gw : ww;
    const float v = src[j];
    if (t < 2) {
        const bf16 h = __float2bfloat16(v);
        wcat_hi[t * 131072 + j] = h;
        wcat_lo[t * 131072 + j] = __float2bfloat16(v - __bfloat162float(h));
    } else if (t == 2) {
        gw16[j] = __float2half(v);
    } else {
        ww16[j] = __float2half(v);
    }
    if (i < 768) {
        const float* bs = (i < 256) ? tb : (i < 512) ? pb : gb;
        bcat[i] = bs[i & 255];
    }
}

// ---------------- transpose x (b,512,N) -> xT bf16 hi/lo + fp16 plane ----------------
__global__ void xpose_kernel(const float* __restrict__ x, bf16* __restrict__ xhi,
                             bf16* __restrict__ xlo, __half* __restrict__ xf)
{
    __shared__ float t[32][33];
    const int b = blockIdx.z;
    const int n0 = blockIdx.x * 32;
    const int c0 = blockIdx.y * 32;
    const int tx = threadIdx.x, ty = threadIdx.y;
    const float* xb = x + (long long)b * CCH * NN;
#pragma unroll
    for (int k = 0; k < 4; k++)
        t[ty + k * 8][tx] = xb[(long long)(c0 + ty + k * 8) * NN + n0 + tx];
    __syncthreads();
    bf16* hb = xhi + (long long)b * NN * CCH;
    bf16* lb = xlo + (long long)b * NN * CCH;
    __half* fb = xf + (long long)b * NN * CCH;
#pragma unroll
    for (int k = 0; k < 4; k++) {
        float v = t[tx][ty + k * 8];
        long long o = (long long)(n0 + ty + k * 8) * CCH + c0 + tx;
        bf16 h = __float2bfloat16(v);
        hb[o] = h;
        lb[o] = __float2bfloat16(v - __bfloat162float(h));
        fb[o] = __float2half(v);
    }
}

// ---------------- 2x2x2 maxpool + own pad-fill (grid covers MP_F rows) ----------------
__global__ void pool_kernel(const __half* __restrict__ g16,
                            const bf16* __restrict__ pH, const bf16* __restrict__ pL,
                            __half* __restrict__ gT,
                            bf16* __restrict__ phphi, bf16* __restrict__ phplo)
{
    const int m = blockIdx.x;      // 0..1663 (>=1568 are pads)
    const int b = blockIdx.y;
    const int ci = threadIdx.x;    // 0..255
    if (m >= MMr) {
        // zero pads: php rows [1568,1664); gt cols [1568,1600)
        long long o = ((long long)b * MP_F + m) * CIn + ci;
        phphi[o] = __ushort_as_bfloat16(0);
        phplo[o] = __ushort_as_bfloat16(0);
        if (m < MP_Y)
            gT[((long long)b * CIn + ci) * MP_Y + m] = __ushort_as_half(0);
        return;
    }
    const int tp = m / 196;
    const int r = m % 196;
    const int hp = r / 14;
    const int wp = r % 14;
    const long long bb = (long long)b * NN;
    float gm = -1e30f, pm = -1e30f;
#pragma unroll
    for (int dt = 0; dt < 2; dt++)
#pragma unroll
        for (int dh = 0; dh < 2; dh++)
#pragma unroll
            for (int dw = 0; dw < 2; dw++) {
                const long long n = (long long)(2 * tp + dt) * 784 + (2 * hp + dh) * 28 + (2 * wp + dw);
                const long long o = (bb + n) * CIn + ci;
                float gv = __half2float(g16[o]);
                float pv = __bfloat162float(pH[o]) + __bfloat162float(pL[o]);
                gm = fmaxf(gm, gv);
                pm = fmaxf(pm, pv);
            }
    {
        long long o = ((long long)b * MP_F + m) * CIn + ci;
        bf16 h = __float2bfloat16(pm);
        phphi[o] = h;
        phplo[o] = __float2bfloat16(pm - __bfloat162float(h));
    }
    gT[((long long)b * CIn + ci) * MP_Y + m] = __float2half(gm);
}

// ---------------- softmax: float4 reads; writes p as one fp16 plane ----------------
__global__ __launch_bounds__(256)
void softmax_kernel(const float* __restrict__ f, __half* __restrict__ pout)
{
    __shared__ float row[MMr];
    __shared__ float red[8];
    const long long r = blockIdx.x;
    const float* p = f + r * MP_F;
    __half* oh = pout + r * MP_Y;
    const int tid = threadIdx.x;
    const int wid = tid >> 5, lane = tid & 31;

    float mx = -1e30f;
    for (int i4 = tid; i4 < MMr / 4; i4 += 256) {
        float4 v = ((const float4*)p)[i4];
        *(float4*)&row[i4 * 4] = v;
        mx = fmaxf(fmaxf(mx, fmaxf(v.x, v.y)), fmaxf(v.z, v.w));
    }
#pragma unroll
    for (int s = 16; s > 0; s >>= 1) mx = fmaxf(mx, __shfl_xor_sync(~0u, mx, s));
    if (lane == 0) red[wid] = mx;
    __syncthreads();
    {
        float t = red[lane & 7];
#pragma unroll
        for (int s = 4; s > 0; s >>= 1) t = fmaxf(t, __shfl_xor_sync(~0u, t, s));
        mx = t;
    }

    float sum = 0.f;
    for (int i = tid; i < MMr; i += 256) {
        float e = __expf(row[i] - mx);
        row[i] = e;
        sum += e;
    }
#pragma unroll
    for (int s = 16; s > 0; s >>= 1) sum += __shfl_xor_sync(~0u, sum, s);
    __syncthreads();
    if (lane == 0) red[wid] = sum;
    __syncthreads();
    {
        float t = red[lane & 7];
#pragma unroll
        for (int s = 4; s > 0; s >>= 1) t += __shfl_xor_sync(~0u, t, s);
        sum = t;
    }
    const float inv = 1.f / sum;

    for (int i = tid; i < MMr; i += 256)
        oh[i] = __float2half(row[i] * inv);
    if (tid < MP_Y - MMr)
        oh[MMr + tid] = __ushort_as_half(0);
}

// ---------------- BN stats from fp16 wy ----------------
__global__ void stats_part(const __half* __restrict__ wy, float* __restrict__ part)
{
    const int c = blockIdx.x * 128 + threadIdx.x;
    const int rb = blockIdx.y;
    const __half* p = wy + (long long)rb * 512 * CCH + c;
    float s = 0.f, ss = 0.f;
    for (int r = 0; r < 512; r++) {
        float v = __half2float(p[(long long)r * CCH]);
        s += v;
        ss += v * v;
    }
    part[(long long)rb * 1024 + c] = s;
    part[(long long)rb * 1024 + 512 + c] = ss;
}

__global__ void stats_fin(const float* __restrict__ part, float* __restrict__ stats)
{
    const int c = threadIdx.x;
    float s = 0.f, ss = 0.f;
    for (int r = 0; r < 98; r++) {
        s += part[r * 1024 + c];
        ss += part[r * 1024 + 512 + c];
    }
    const float cnt = (float)BB * (float)NN;
    const float mean = s / cnt;
    const float var = ss / cnt - mean * mean;
    stats[c] = mean;
    stats[CCH + c] = rsqrtf(var + EPS);
}

// ---------------- final: transpose fp16 wy, BN affine + residual ----------------
__global__ void final_kernel(const __half* __restrict__ wy, const float* __restrict__ x,
                             const float* __restrict__ gamma, const float* __restrict__ beta,
                             const float* __restrict__ stats, float* __restrict__ out)
{
    __shared__ __half t[32][34];
    const int b = blockIdx.z;
    const int n0 = blockIdx.x * 32;
    const int c0 = blockIdx.y * 32;
    const int tx = threadIdx.x, ty = threadIdx.y;
    const __half* wb = wy + (long long)b * NN * CCH;
#pragma unroll
    for (int k = 0; k < 4; k++)
        t[ty + k * 8][tx] = wb[(long long)(n0 + ty + k * 8) * CCH + c0 + tx];
    __syncthreads();
#pragma unroll
    for (int k = 0; k < 4; k++) {
        const int c = c0 + ty + k * 8;
        const float mean = stats[c];
        const float rstd = stats[CCH + c];
        const float gs = gamma[c] * rstd;
        const float off = beta[c] - mean * gs;
        const long long o = ((long long)b * CCH + c) * NN + n0 + tx;
        out[o] = __half2float(t[tx][ty + k * 8]) * gs + off + x[o];
    }
}

// ---------------- launch ----------------
extern "C" void kernel_launch(void* const* d_in, const int* in_sizes, int n_in,
                              void* d_out, int out_size)
{
    const float* x       = (const float*)d_in[0];
    const float* g_w     = (const float*)d_in[1];
    const float* g_b     = (const float*)d_in[2];
    const float* theta_w = (const float*)d_in[3];
    const float* theta_b = (const float*)d_in[4];
    const float* phi_w   = (const float*)d_in[5];
    const float* phi_b   = (const float*)d_in[6];
    const float* W_w     = (const float*)d_in[7];
    // d_in[8] = W_b: constant channel bias cancels exactly in training-mode BN — skipped.
    const float* gamma   = (const float*)d_in[9];
    const float* beta    = (const float*)d_in[10];
    float* out = (float*)d_out;

    unsigned char* S = nullptr;
    float* stats = nullptr;
    cudaGetSymbolAddress((void**)&S, d_scratch);
    cudaGetSymbolAddress((void**)&stats, d_stats);

    bf16* xt_hi  = (bf16*)(S + XT_HI);
    bf16* xt_lo  = (bf16*)(S + XT_LO);
    __half* xt16 = (__half*)(S + XT_F16);
    float* f     = (float*)(S + F_OFF);
    bf16* conv_hi = (bf16*)(S + CONV_HI);
    bf16* conv_lo = (bf16*)(S + CONV_LO);
    bf16* th_hi  = conv_hi;
    bf16* th_lo  = conv_lo;
    bf16* pc_hi  = (bf16*)(S + CONV_HI + CONV_PLANE);
    bf16* pc_lo  = (bf16*)(S + CONV_LO + CONV_PLANE);
    __half* g16  = (__half*)(S + G16_OFF);
    __half* p16  = (__half*)(S + P_F16);
    __half* y16  = (__half*)(S + Y_F16);
    __half* wy   = (__half*)(S + WY_OFF);
    __half* gt16 = (__half*)(S + GT_F16);
    bf16* php_hi = (bf16*)(S + PHP_HI);
    bf16* php_lo = (bf16*)(S + PHP_LO);
    bf16* wcat_hi = (bf16*)(S + W8_OFF);
    bf16* wcat_lo = (bf16*)(S + W8_OFF + 524288);
    __half* gw16 = (__half*)(S + W8_OFF + 1048576);
    __half* ww16 = (__half*)(S + W8_OFF + 1310720);
    float* bcat  = (float*)(S + BCAT_OFF);
    float* part  = (float*)(S + PART_OFF);

    const int smem = 3 * 32768;
    cudaFuncSetAttribute(tgemm<0, 0, 3, 0, MMr>, cudaFuncAttributeMaxDynamicSharedMemorySize, smem);
    cudaFuncSetAttribute(tgemm<2, 0, 1, 1, 0>, cudaFuncAttributeMaxDynamicSharedMemorySize, smem);
    cudaFuncSetAttribute(tgemm<1, 1, 3, 0, 0>, cudaFuncAttributeMaxDynamicSharedMemorySize, smem);

    const long long sXT = (long long)NN * CCH;
    const long long sCI = (long long)NN * CIn;

    // launch 0: weight splits + bias concat
    prep_kernel<<<2048, 256>>>(theta_w, phi_w, g_w, W_w, theta_b, phi_b, g_b,
                               wcat_hi, wcat_lo, gw16, ww16, bcat);

    // launch 1: transpose x -> xT bf16 hi/lo + fp16 plane
    xpose_kernel<<<dim3(NN / 32, CCH / 32, BB), dim3(32, 8)>>>(x, xt_hi, xt_lo, xt16);

    // launch 2: fused conv [theta|phi] 3-pass bf16
    tgemm<1, 1, 3, 0, 0><<<dim3(98, 4, BB), 256, smem>>>(xt_hi, xt_lo, wcat_hi, wcat_lo,
        nullptr, conv_hi, conv_lo, bcat, CCH, CIn, sXT, 0LL, sCI, 4LL * sCI);

    // launch 3: g conv 1-pass fp16
    tgemm<2, 0, 1, 1, 0><<<dim3(98, 2, BB), 256, smem>>>(
        (const bf16*)xt16, (const bf16*)xt16, (const bf16*)gw16, (const bf16*)gw16,
        nullptr, (bf16*)g16, nullptr, bcat + 512, CCH, CIn, sXT, 0LL, sCI, 0LL);

    // launch 4: pool (covers pads; no separate zero kernel)
    pool_kernel<<<dim3(MP_F, BB), 256>>>(g16, pc_hi, pc_lo, gt16, php_hi, php_lo);

    // launch 5: f = theta @ phi^T, 3-pass bf16 (validated core), clip dead cols
    tgemm<0, 0, 3, 0, MMr><<<dim3(98, MP_F / 128, BB), 256, smem>>>(th_hi, th_lo,
        php_hi, php_lo, f, nullptr, nullptr, nullptr, CIn, MP_F, sCI,
        (long long)MP_F * CIn, (long long)NN * MP_F, 0LL);

    // launch 6: softmax -> p fp16
    softmax_kernel<<<BB * NN, 256>>>(f, p16);

    // launch 7: y = p @ gT^T, 1-pass fp16
    tgemm<2, 0, 1, 1, 0><<<dim3(98, 2, BB), 256, smem>>>(
        (const bf16*)p16, (const bf16*)p16, (const bf16*)gt16, (const bf16*)gt16,
        nullptr, (bf16*)y16, nullptr, nullptr, MP_Y, CIn, (long long)NN * MP_Y,
        (long long)CIn * MP_Y, sCI, 0LL);

    // launch 8: wy = y @ W^T, 1-pass fp16 -> fp16 wy
    tgemm<2, 0, 1, 1, 0><<<dim3(98, 4, BB), 256, smem>>>(
        (const bf16*)y16, (const bf16*)y16, (const bf16*)ww16, (const bf16*)ww16,
        nullptr, (bf16*)wy, nullptr, nullptr, CIn, CCH, sCI, 0LL, (long long)NN * CCH, 0LL);

    // launches 9-10: BN stats
    stats_part<<<dim3(4, 98), 128>>>(wy, part);
    stats_fin<<<1, 512>>>(part, stats);

    // launch 11: transpose + BN affine + residual
    final_kernel<<<dim3(NN / 32, CCH / 32, BB), dim3(32, 8)>>>(wy, x, gamma, beta, stats, out);
}

// round 17
// speedup vs baseline: 1.0847x; 1.0045x over previous
#include <cuda_runtime.h>
#include <cuda_bf16.h>
#include <cuda_fp16.h>
#include <stdint.h>
#include <math.h>

typedef __nv_bfloat16 bf16;
typedef unsigned int u32;

// ---------------- problem constants ----------------
#define BB 4
#define CCH 512
#define CIn 256
#define NN 12544
#define MMr 1568          // real pooled positions
#define MP_Y 1600         // pad for y-GEMM K (25*64)
#define MP_F 1664         // pad for f-GEMM N (13*128)
#define EPS 1e-5f

// ---------------- scratch layout (byte offsets) ----------------
#define XT_HI    0ULL
#define XT_LO    51380224ULL
#define XT_F16   102760448ULL
#define F_OFF    0ULL
#define CONV_HI  334987264ULL                   // [theta_hi | phi_hi]
#define G16_OFF  386367488ULL                   // g conv out, fp16 single plane
#define CONV_LO  412057600ULL                   // [theta_lo | phi_lo]
#define P_F16    334987264ULL
#define Y_F16    0ULL
#define WY_OFF   102760448ULL                   // fp16 wy
#define GT_F16   656113664ULL
#define PHP_HI   662667264ULL
#define PHP_LO   666075136ULL
#define W8_OFF   669483008ULL
#define BCAT_OFF 671580160ULL
#define PART_OFF 671583232ULL
#define SCRATCH_BYTES 672000000ULL

#define CONV_PLANE 25690112ULL   // bytes per conv plane (4*NN*256*2)

__device__ __align__(128) unsigned char d_scratch[SCRATCH_BYTES];
__device__ __align__(16) float d_stats[2 * CCH];

// ---------------- helpers ----------------
__device__ __forceinline__ u32 smem_u32(const void* p) {
    u32 a;
    asm("{ .reg .u64 t; cvta.to.shared.u64 t, %1; cvt.u32.u64 %0, t; }" : "=r"(a) : "l"(p));
    return a;
}
__device__ __forceinline__ void ldsm4(u32& r0, u32& r1, u32& r2, u32& r3, u32 addr) {
    asm volatile("ldmatrix.sync.aligned.m8n8.x4.shared.b16 {%0,%1,%2,%3}, [%4];"
                 : "=r"(r0), "=r"(r1), "=r"(r2), "=r"(r3) : "r"(addr));
}
template <int F16>
__device__ __forceinline__ void mma16816(float* d, const u32* a, const u32* b) {
    if (F16)
        asm volatile(
            "mma.sync.aligned.m16n8k16.row.col.f32.f16.f16.f32 "
            "{%0,%1,%2,%3},{%4,%5,%6,%7},{%8,%9},{%0,%1,%2,%3};"
            : "+f"(d[0]), "+f"(d[1]), "+f"(d[2]), "+f"(d[3])
            : "r"(a[0]), "r"(a[1]), "r"(a[2]), "r"(a[3]), "r"(b[0]), "r"(b[1]));
    else
        asm volatile(
            "mma.sync.aligned.m16n8k16.row.col.f32.bf16.bf16.f32 "
            "{%0,%1,%2,%3},{%4,%5,%6,%7},{%8,%9},{%0,%1,%2,%3};"
            : "+f"(d[0]), "+f"(d[1]), "+f"(d[2]), "+f"(d[3])
            : "r"(a[0]), "r"(a[1]), "r"(a[2]), "r"(a[3]), "r"(b[0]), "r"(b[1]));
}
__device__ __forceinline__ u32 sw128(u32 off) { return off ^ ((off >> 3) & 0x70); }
__device__ __forceinline__ void cp16(u32 dst, const void* src) {
    asm volatile("cp.async.cg.shared.global [%0], [%1], 16;" :: "r"(dst), "l"(src));
}
#define CP_COMMIT() asm volatile("cp.async.commit_group;" ::: "memory")
#define CP_WAIT1()  asm volatile("cp.async.wait_group 1;" ::: "memory")

// ---------------- cp.async split 16-bit GEMM (R7-validated core) ----------------
// Passes: 0 = A_hi*B_hi^T, 1 = A_hi*B_lo^T, 2 = A_lo*B_hi^T.
// NP=3: full 3-term split. NP=1: plain A_hi*B_hi^T.
// CTA tile 128x128, BK=64, 8 warps (2M x 4N), 3-stage cp.async ring, 2 CTAs/SM.
// EPI 0: fp32 C + optional col bias (cols >= CLIP skipped). EPI 1: bf16 hi/lo planes.
// EPI 2: single fp16 plane.
// SEG 1: 256-col segmented output (fused conv). F16: fp16 mma instead of bf16.
// CLIP: if >0, EPI-0 stores only columns < CLIP.
template <int EPI, int SEG, int NP, int F16, int CLIP>
__global__ __launch_bounds__(256, 2)
void tgemm(const bf16* __restrict__ Ahi, const bf16* __restrict__ Alo,
           const bf16* __restrict__ Bhi, const bf16* __restrict__ Blo,
           float* __restrict__ Cf, bf16* __restrict__ Chi, bf16* __restrict__ Clo,
           const float* __restrict__ bias,
           int K, int ldc, long long sA, long long sB, long long sC, long long segS)
{
    extern __shared__ __align__(1024) unsigned char sm[];
    const u32 sbase = smem_u32(sm);
    const int tid = threadIdx.x;
    const int wid = tid >> 5;
    const int lane = tid & 31;
    const int m0 = blockIdx.x * 128;
    const int n0 = blockIdx.y * 128;
    const long long bz = blockIdx.z;
    Ahi += bz * sA; Alo += bz * sA;
    Bhi += bz * sB; Blo += bz * sB;

    const int Kc = K >> 6;
    const int total = NP * Kc;

    const int rowL = tid >> 1;
    const int segb = (tid & 1) * 32;
    const long long gA = (long long)(m0 + rowL) * K + segb;
    const long long gB = (long long)(n0 + rowL) * K + segb;
    u32 soff[4];
#pragma unroll
    for (int i = 0; i < 4; i++)
        soff[i] = sw128((u32)rowL * 128 + (u32)segb * 2 + i * 16);

#define ISSUE(it2) do { \
    const int _p = (it2) / Kc; \
    const int _k0 = ((it2) - _p * Kc) << 6; \
    const bf16* _A = (_p == 2) ? Alo : Ahi; \
    const bf16* _B = (_p == 1) ? Blo : Bhi; \
    const u32 _sa = sbase + ((it2) % 3) * 32768u; \
    const u32 _sb = _sa + 16384u; \
    _Pragma("unroll") \
    for (int _i = 0; _i < 4; _i++) { \
        cp16(_sa + soff[_i], _A + gA + _k0 + _i * 8); \
        cp16(_sb + soff[_i], _B + gB + _k0 + _i * 8); \
    } \
} while (0)

    const int wm = wid >> 2;
    const int wn = wid & 3;
    const int rowA = wm * 64 + ((lane >> 3) & 1) * 8 + (lane & 7);
    const u32 kbA = (u32)(lane >> 4) * 16;
    const int rowB = wn * 32 + ((lane >> 4) & 1) * 8 + (lane & 7);
    const u32 kbB = (u32)((lane >> 3) & 1) * 16;

    float acc[4][4][4];
#pragma unroll
    for (int mt = 0; mt < 4; mt++)
#pragma unroll
        for (int nt = 0; nt < 4; nt++)
#pragma unroll
            for (int q = 0; q < 4; q++) acc[mt][nt][q] = 0.f;

    ISSUE(0); CP_COMMIT();
    ISSUE(1); CP_COMMIT();

    for (int it = 0; it < total; it++) {
        CP_WAIT1();
        __syncthreads();
        if (it + 2 < total) ISSUE(it + 2);
        CP_COMMIT();

        const u32 sA32 = sbase + (it % 3) * 32768u;
        const u32 sB32 = sA32 + 16384u;
#pragma unroll
        for (int kk = 0; kk < 4; kk++) {
            u32 af[4][4];
#pragma unroll
            for (int mt = 0; mt < 4; mt++) {
                u32 off = (u32)(rowA + mt * 16) * 128 + (u32)kk * 32 + kbA;
                ldsm4(af[mt][0], af[mt][1], af[mt][2], af[mt][3], sA32 + sw128(off));
            }
            u32 bfr[2][4];
#pragma unroll
            for (int nt2 = 0; nt2 < 2; nt2++) {
                u32 off = (u32)(rowB + nt2 * 16) * 128 + (u32)kk * 32 + kbB;
                ldsm4(bfr[nt2][0], bfr[nt2][1], bfr[nt2][2], bfr[nt2][3], sB32 + sw128(off));
            }
#pragma unroll
            for (int mt = 0; mt < 4; mt++)
#pragma unroll
                for (int nt = 0; nt < 4; nt++)
                    mma16816<F16>(acc[mt][nt], af[mt], &bfr[nt >> 1][(nt & 1) * 2]);
        }
    }
#undef ISSUE

    const int r0 = m0 + wm * 64 + (lane >> 2);
    const int cb0 = n0 + wn * 32 + (lane & 3) * 2;
    const long long obase = bz * sC + (SEG ? (long long)(n0 >> 8) * segS : 0LL);
#pragma unroll
    for (int nt = 0; nt < 4; nt++) {
        const int c = cb0 + nt * 8;
        const int cl = SEG ? (c & 255) : c;
        if (CLIP > 0 && c >= CLIP) continue;
        const float b0v = bias ? bias[c] : 0.f;
        const float b1v = bias ? bias[c + 1] : 0.f;
#pragma unroll
        for (int mt = 0; mt < 4; mt++) {
            const long long ra = r0 + mt * 16;
            const long long rb = ra + 8;
            float v0 = acc[mt][nt][0] + b0v;
            float v1 = acc[mt][nt][1] + b1v;
            float v2 = acc[mt][nt][2] + b0v;
            float v3 = acc[mt][nt][3] + b1v;
            if (EPI == 0) {
                float* base = Cf + obase;
                *(float2*)(base + ra * ldc + cl) = make_float2(v0, v1);
                *(float2*)(base + rb * ldc + cl) = make_float2(v2, v3);
            } else if (EPI == 2) {
                __half* hp = (__half*)Chi + obase;
                *(__half2*)(hp + ra * ldc + cl) = __floats2half2_rn(v0, v1);
                *(__half2*)(hp + rb * ldc + cl) = __floats2half2_rn(v2, v3);
            } else {
                bf16 h0 = __float2bfloat16(v0), h1 = __float2bfloat16(v1);
                bf16 h2 = __float2bfloat16(v2), h3 = __float2bfloat16(v3);
                bf16 l0 = __float2bfloat16(v0 - __bfloat162float(h0));
                bf16 l1 = __float2bfloat16(v1 - __bfloat162float(h1));
                bf16 l2 = __float2bfloat16(v2 - __bfloat162float(h2));
                bf16 l3 = __float2bfloat16(v3 - __bfloat162float(h3));
                bf16* hb = Chi + obase;
                bf16* lb = Clo + obase;
                *(u32*)(hb + ra * ldc + cl) = (u32)__bfloat16_as_ushort(h0) | ((u32)__bfloat16_as_ushort(h1) << 16);
                *(u32*)(hb + rb * ldc + cl) = (u32)__bfloat16_as_ushort(h2) | ((u32)__bfloat16_as_ushort(h3) << 16);
                *(u32*)(lb + ra * ldc + cl) = (u32)__bfloat16_as_ushort(l0) | ((u32)__bfloat16_as_ushort(l1) << 16);
                *(u32*)(lb + rb * ldc + cl) = (u32)__bfloat16_as_ushort(l2) | ((u32)__bfloat16_as_ushort(l3) << 16);
            }
        }
    }
}

// ---------------- prep: theta/phi bf16 hi/lo, g/W fp16 single; bias concat ----------------
__global__ void prep_kernel(const float* __restrict__ tw, const float* __restrict__ pw,
                            const float* __restrict__ gw, const float* __restrict__ ww,
                            const float* __restrict__ tb, const float* __restrict__ pb,
                            const float* __restrict__ gb,
                            bf16* __restrict__ wcat_hi, bf16* __restrict__ wcat_lo,
                            __half* __restrict__ gw16, __half* __restrict__ ww16,
                            float* __restrict__ bcat)
{
    const int i = blockIdx.x * 256 + threadIdx.x;
    const int t = i >> 17;
    const int j = i & 131071;
    const float* src = (t == 0) ? tw : (t == 1) ? pw : (t == 2) ? gw : ww;
    const float v = src[j];
    if (t < 2) {
        const bf16 h = __float2bfloat16(v);
        wcat_hi[t * 131072 + j] = h;
        wcat_lo[t * 131072 + j] = __float2bfloat16(v - __bfloat162float(h));
    } else if (t == 2) {
        gw16[j] = __float2half(v);
    } else {
        ww16[j] = __float2half(v);
    }
    if (i < 768) {
        const float* bs = (i < 256) ? tb : (i < 512) ? pb : gb;
        bcat[i] = bs[i & 255];
    }
}

// ---------------- transpose x (b,512,N) -> xT bf16 hi/lo + fp16 plane ----------------
__global__ void xpose_kernel(const float* __restrict__ x, bf16* __restrict__ xhi,
                             bf16* __restrict__ xlo, __half* __restrict__ xf)
{
    __shared__ float t[32][33];
    const int b = blockIdx.z;
    const int n0 = blockIdx.x * 32;
    const int c0 = blockIdx.y * 32;
    const int tx = threadIdx.x, ty = threadIdx.y;
    const float* xb = x + (long long)b * CCH * NN;
#pragma unroll
    for (int k = 0; k < 4; k++)
        t[ty + k * 8][tx] = xb[(long long)(c0 + ty + k * 8) * NN + n0 + tx];
    __syncthreads();
    bf16* hb = xhi + (long long)b * NN * CCH;
    bf16* lb = xlo + (long long)b * NN * CCH;
    __half* fb = xf + (long long)b * NN * CCH;
#pragma unroll
    for (int k = 0; k < 4; k++) {
        float v = t[tx][ty + k * 8];
        long long o = (long long)(n0 + ty + k * 8) * CCH + c0 + tx;
        bf16 h = __float2bfloat16(v);
        hb[o] = h;
        lb[o] = __float2bfloat16(v - __bfloat162float(h));
        fb[o] = __float2half(v);
    }
}

// ---------------- 2x2x2 maxpool + own pad-fill (grid covers MP_F rows) ----------------
__global__ void pool_kernel(const __half* __restrict__ g16,
                            const bf16* __restrict__ pH, const bf16* __restrict__ pL,
                            __half* __restrict__ gT,
                            bf16* __restrict__ phphi, bf16* __restrict__ phplo)
{
    const int m = blockIdx.x;      // 0..1663 (>=1568 are pads)
    const int b = blockIdx.y;
    const int ci = threadIdx.x;    // 0..255
    if (m >= MMr) {
        long long o = ((long long)b * MP_F + m) * CIn + ci;
        phphi[o] = __ushort_as_bfloat16(0);
        phplo[o] = __ushort_as_bfloat16(0);
        if (m < MP_Y)
            gT[((long long)b * CIn + ci) * MP_Y + m] = __ushort_as_half(0);
        return;
    }
    const int tp = m / 196;
    const int r = m % 196;
    const int hp = r / 14;
    const int wp = r % 14;
    const long long bb = (long long)b * NN;
    float gm = -1e30f, pm = -1e30f;
#pragma unroll
    for (int dt = 0; dt < 2; dt++)
#pragma unroll
        for (int dh = 0; dh < 2; dh++)
#pragma unroll
            for (int dw = 0; dw < 2; dw++) {
                const long long n = (long long)(2 * tp + dt) * 784 + (2 * hp + dh) * 28 + (2 * wp + dw);
                const long long o = (bb + n) * CIn + ci;
                float gv = __half2float(g16[o]);
                float pv = __bfloat162float(pH[o]) + __bfloat162float(pL[o]);
                gm = fmaxf(gm, gv);
                pm = fmaxf(pm, pv);
            }
    {
        long long o = ((long long)b * MP_F + m) * CIn + ci;
        bf16 h = __float2bfloat16(pm);
        phphi[o] = h;
        phplo[o] = __float2bfloat16(pm - __bfloat162float(h));
    }
    gT[((long long)b * CIn + ci) * MP_Y + m] = __float2half(gm);
}

// ---------------- softmax: float4 reads, half2 writes ----------------
__global__ __launch_bounds__(256)
void softmax_kernel(const float* __restrict__ f, __half* __restrict__ pout)
{
    __shared__ float row[MMr];
    __shared__ float red[8];
    const long long r = blockIdx.x;
    const float* p = f + r * MP_F;
    __half2* oh2 = (__half2*)(pout + r * MP_Y);
    const int tid = threadIdx.x;
    const int wid = tid >> 5, lane = tid & 31;

    float mx = -1e30f;
    for (int i4 = tid; i4 < MMr / 4; i4 += 256) {
        float4 v = ((const float4*)p)[i4];
        *(float4*)&row[i4 * 4] = v;
        mx = fmaxf(fmaxf(mx, fmaxf(v.x, v.y)), fmaxf(v.z, v.w));
    }
#pragma unroll
    for (int s = 16; s > 0; s >>= 1) mx = fmaxf(mx, __shfl_xor_sync(~0u, mx, s));
    if (lane == 0) red[wid] = mx;
    __syncthreads();
    {
        float t = red[lane & 7];
#pragma unroll
        for (int s = 4; s > 0; s >>= 1) t = fmaxf(t, __shfl_xor_sync(~0u, t, s));
        mx = t;
    }

    float sum = 0.f;
    for (int i = tid; i < MMr; i += 256) {
        float e = __expf(row[i] - mx);
        row[i] = e;
        sum += e;
    }
#pragma unroll
    for (int s = 16; s > 0; s >>= 1) sum += __shfl_xor_sync(~0u, sum, s);
    __syncthreads();
    if (lane == 0) red[wid] = sum;
    __syncthreads();
    {
        float t = red[lane & 7];
#pragma unroll
        for (int s = 4; s > 0; s >>= 1) t += __shfl_xor_sync(~0u, t, s);
        sum = t;
    }
    const float inv = 1.f / sum;

    for (int i2 = tid; i2 < MMr / 2; i2 += 256)
        oh2[i2] = __floats2half2_rn(row[i2 * 2] * inv, row[i2 * 2 + 1] * inv);
    if (tid < (MP_Y - MMr) / 2)
        oh2[MMr / 2 + tid] = __floats2half2_rn(0.f, 0.f);
}

// ---------------- BN stats from fp16 wy ----------------
__global__ void stats_part(const __half* __restrict__ wy, float* __restrict__ part)
{
    const int c = blockIdx.x * 128 + threadIdx.x;
    const int rb = blockIdx.y;
    const __half* p = wy + (long long)rb * 512 * CCH + c;
    float s = 0.f, ss = 0.f;
    for (int r = 0; r < 512; r++) {
        float v = __half2float(p[(long long)r * CCH]);
        s += v;
        ss += v * v;
    }
    part[(long long)rb * 1024 + c] = s;
    part[(long long)rb * 1024 + 512 + c] = ss;
}

__global__ void stats_fin(const float* __restrict__ part, float* __restrict__ stats)
{
    const int c = threadIdx.x;
    float s = 0.f, ss = 0.f;
    for (int r = 0; r < 98; r++) {
        s += part[r * 1024 + c];
        ss += part[r * 1024 + 512 + c];
    }
    const float cnt = (float)BB * (float)NN;
    const float mean = s / cnt;
    const float var = ss / cnt - mean * mean;
    stats[c] = mean;
    stats[CCH + c] = rsqrtf(var + EPS);
}

// ---------------- final: 64n x 32c tile, coalesced wy/x/out ----------------
__global__ void final_kernel(const __half* __restrict__ wy, const float* __restrict__ x,
                             const float* __restrict__ gamma, const float* __restrict__ beta,
                             const float* __restrict__ stats, float* __restrict__ out)
{
    __shared__ __half t[32][66];
    const int b = blockIdx.z;
    const int n0 = blockIdx.x * 64;
    const int c0 = blockIdx.y * 32;
    const int tx = threadIdx.x, ty = threadIdx.y;   // 32 x 8
    const __half* wb = wy + (long long)b * NN * CCH;
    // load: 64 n-rows, each row 32 contiguous c-halves (coalesced 64B)
#pragma unroll
    for (int k = 0; k < 8; k++) {
        const int nl = ty + k * 8;
        t[tx][nl] = wb[(long long)(n0 + nl) * CCH + c0 + tx];
    }
    __syncthreads();
    // store: each warp writes two 128B-coalesced lines per k
#pragma unroll
    for (int k = 0; k < 4; k++) {
        const int c = c0 + ty + k * 8;
        const float mean = stats[c];
        const float rstd = stats[CCH + c];
        const float gs = gamma[c] * rstd;
        const float off = beta[c] - mean * gs;
        const long long o = ((long long)b * CCH + c) * NN + n0 + tx;
        out[o]      = __half2float(t[ty + k * 8][tx])      * gs + off + x[o];
        out[o + 32] = __half2float(t[ty + k * 8][tx + 32]) * gs + off + x[o + 32];
    }
}

// ---------------- launch ----------------
extern "C" void kernel_launch(void* const* d_in, const int* in_sizes, int n_in,
                              void* d_out, int out_size)
{
    const float* x       = (const float*)d_in[0];
    const float* g_w     = (const float*)d_in[1];
    const float* g_b     = (const float*)d_in[2];
    const float* theta_w = (const float*)d_in[3];
    const float* theta_b = (const float*)d_in[4];
    const float* phi_w   = (const float*)d_in[5];
    const float* phi_b   = (const float*)d_in[6];
    const float* W_w     = (const float*)d_in[7];
    // d_in[8] = W_b: constant channel bias cancels exactly in training-mode BN — skipped.
    const float* gamma   = (const float*)d_in[9];
    const float* beta    = (const float*)d_in[10];
    float* out = (float*)d_out;

    unsigned char* S = nullptr;
    float* stats = nullptr;
    cudaGetSymbolAddress((void**)&S, d_scratch);
    cudaGetSymbolAddress((void**)&stats, d_stats);

    bf16* xt_hi  = (bf16*)(S + XT_HI);
    bf16* xt_lo  = (bf16*)(S + XT_LO);
    __half* xt16 = (__half*)(S + XT_F16);
    float* f     = (float*)(S + F_OFF);
    bf16* conv_hi = (bf16*)(S + CONV_HI);
    bf16* conv_lo = (bf16*)(S + CONV_LO);
    bf16* th_hi  = conv_hi;
    bf16* th_lo  = conv_lo;
    bf16* pc_hi  = (bf16*)(S + CONV_HI + CONV_PLANE);
    bf16* pc_lo  = (bf16*)(S + CONV_LO + CONV_PLANE);
    __half* g16  = (__half*)(S + G16_OFF);
    __half* p16  = (__half*)(S + P_F16);
    __half* y16  = (__half*)(S + Y_F16);
    __half* wy   = (__half*)(S + WY_OFF);
    __half* gt16 = (__half*)(S + GT_F16);
    bf16* php_hi = (bf16*)(S + PHP_HI);
    bf16* php_lo = (bf16*)(S + PHP_LO);
    bf16* wcat_hi = (bf16*)(S + W8_OFF);
    bf16* wcat_lo = (bf16*)(S + W8_OFF + 524288);
    __half* gw16 = (__half*)(S + W8_OFF + 1048576);
    __half* ww16 = (__half*)(S + W8_OFF + 1310720);
    float* bcat  = (float*)(S + BCAT_OFF);
    float* part  = (float*)(S + PART_OFF);

    const int smem = 3 * 32768;
    cudaFuncSetAttribute(tgemm<0, 0, 3, 0, MMr>, cudaFuncAttributeMaxDynamicSharedMemorySize, smem);
    cudaFuncSetAttribute(tgemm<2, 0, 1, 1, 0>, cudaFuncAttributeMaxDynamicSharedMemorySize, smem);
    cudaFuncSetAttribute(tgemm<1, 1, 3, 0, 0>, cudaFuncAttributeMaxDynamicSharedMemorySize, smem);

    const long long sXT = (long long)NN * CCH;
    const long long sCI = (long long)NN * CIn;

    // launch 0: weight splits + bias concat
    prep_kernel<<<2048, 256>>>(theta_w, phi_w, g_w, W_w, theta_b, phi_b, g_b,
                               wcat_hi, wcat_lo, gw16, ww16, bcat);

    // launch 1: transpose x -> xT bf16 hi/lo + fp16 plane
    xpose_kernel<<<dim3(NN / 32, CCH / 32, BB), dim3(32, 8)>>>(x, xt_hi, xt_lo, xt16);

    // launch 2: fused conv [theta|phi] 3-pass bf16
    tgemm<1, 1, 3, 0, 0><<<dim3(98, 4, BB), 256, smem>>>(xt_hi, xt_lo, wcat_hi, wcat_lo,
        nullptr, conv_hi, conv_lo, bcat, CCH, CIn, sXT, 0LL, sCI, 4LL * sCI);

    // launch 3: g conv 1-pass fp16
    tgemm<2, 0, 1, 1, 0><<<dim3(98, 2, BB), 256, smem>>>(
        (const bf16*)xt16, (const bf16*)xt16, (const bf16*)gw16, (const bf16*)gw16,
        nullptr, (bf16*)g16, nullptr, bcat + 512, CCH, CIn, sXT, 0LL, sCI, 0LL);

    // launch 4: pool (covers pads)
    pool_kernel<<<dim3(MP_F, BB), 256>>>(g16, pc_hi, pc_lo, gt16, php_hi, php_lo);

    // launch 5: f = theta @ phi^T, 3-pass bf16 (validated core), clip dead cols
    tgemm<0, 0, 3, 0, MMr><<<dim3(98, MP_F / 128, BB), 256, smem>>>(th_hi, th_lo,
        php_hi, php_lo, f, nullptr, nullptr, nullptr, CIn, MP_F, sCI,
        (long long)MP_F * CIn, (long long)NN * MP_F, 0LL);

    // launch 6: softmax -> p fp16
    softmax_kernel<<<BB * NN, 256>>>(f, p16);

    // launch 7: y = p @ gT^T, 1-pass fp16
    tgemm<2, 0, 1, 1, 0><<<dim3(98, 2, BB), 256, smem>>>(
        (const bf16*)p16, (const bf16*)p16, (const bf16*)gt16, (const bf16*)gt16,
        nullptr, (bf16*)y16, nullptr, nullptr, MP_Y, CIn, (long long)NN * MP_Y,
        (long long)CIn * MP_Y, sCI, 0LL);

    // launch 8: wy = y @ W^T, 1-pass fp16 -> fp16 wy
    tgemm<2, 0, 1, 1, 0><<<dim3(98, 4, BB), 256, smem>>>(
        (const bf16*)y16, (const bf16*)y16, (const bf16*)ww16, (const bf16*)ww16,
        nullptr, (bf16*)wy, nullptr, nullptr, CIn, CCH, sCI, 0LL, (long long)NN * CCH, 0LL);

    // launches 9-10: BN stats
    stats_part<<<dim3(4, 98), 128>>>(wy, part);
    stats_fin<<<1, 512>>>(part, stats);

    // launch 11: transpose + BN affine + residual (64n x 32c tiles)
    final_kernel<<<dim3(NN / 64, CCH / 32, BB), dim3(32, 8)>>>(wy, x, gamma, beta, stats, out);
}